// round 10
// baseline (speedup 1.0000x reference)
#include <cuda_runtime.h>
#include <cuda_bf16.h>
#include <math.h>
#include <stdint.h>

#define DMODEL 1024
#define NHEAD  16
#define HD     64
#define NB     4
#define SQ     1024
#define SK     2048

// ---------------------------------------------------------------------------
// Scratch (__device__ globals: allocation-free rule)
// ---------------------------------------------------------------------------
__device__ __nv_bfloat16 g_qh[NB * SQ * DMODEL];
__device__ __nv_bfloat16 g_ql[NB * SQ * DMODEL];
__device__ __nv_bfloat16 g_kvh[NB * SK * DMODEL];
__device__ __nv_bfloat16 g_kvl[NB * SK * DMODEL];
__device__ __nv_bfloat16 g_oh[NB * SQ * DMODEL];
__device__ __nv_bfloat16 g_ol[NB * SQ * DMODEL];
__device__ __nv_bfloat16 g_wqh[DMODEL * DMODEL];
__device__ __nv_bfloat16 g_wql[DMODEL * DMODEL];
__device__ __nv_bfloat16 g_wkh[DMODEL * DMODEL];
__device__ __nv_bfloat16 g_wkl[DMODEL * DMODEL];
__device__ __nv_bfloat16 g_wvh[DMODEL * DMODEL];
__device__ __nv_bfloat16 g_wvl[DMODEL * DMODEL];
__device__ __nv_bfloat16 g_woh[DMODEL * DMODEL];
__device__ __nv_bfloat16 g_wol[DMODEL * DMODEL];

// attention operands (bf16 hi/lo, post-RoPE, written by fused gemm epilogues)
__device__ __nv_bfloat16 g_aqh[NB * SQ * DMODEL];
__device__ __nv_bfloat16 g_aql[NB * SQ * DMODEL];
__device__ __nv_bfloat16 g_akh[NB * SK * DMODEL];
__device__ __nv_bfloat16 g_akl[NB * SK * DMODEL];
__device__ __nv_bfloat16 g_avh[NB * SK * DMODEL];
__device__ __nv_bfloat16 g_avl[NB * SK * DMODEL];

// ---------------------------------------------------------------------------
// Helpers
// ---------------------------------------------------------------------------
__device__ __forceinline__ uint32_t smem_u32(const void* p) {
    uint32_t a;
    asm("{ .reg .u64 t; cvta.to.shared.u64 t, %1; cvt.u32.u64 %0, t; }" : "=r"(a) : "l"(p));
    return a;
}
__device__ __forceinline__ void cp16(uint32_t dst, const void* src) {
    asm volatile("cp.async.cg.shared.global [%0], [%1], 16;" :: "r"(dst), "l"(src));
}
__device__ __forceinline__ void cp_commit() {
    asm volatile("cp.async.commit_group;" ::: "memory");
}
__device__ __forceinline__ void cp_wait1() {
    asm volatile("cp.async.wait_group 1;" ::: "memory");
}
__device__ __forceinline__ void cp_wait0() {
    asm volatile("cp.async.wait_group 0;" ::: "memory");
}
__device__ __forceinline__ void ldsm_x4(uint32_t addr, uint32_t* r) {
    asm volatile("ldmatrix.sync.aligned.m8n8.x4.shared.b16 {%0,%1,%2,%3}, [%4];"
                 : "=r"(r[0]), "=r"(r[1]), "=r"(r[2]), "=r"(r[3]) : "r"(addr));
}
__device__ __forceinline__ void ldsm_x4t(uint32_t addr, uint32_t* r) {
    asm volatile("ldmatrix.sync.aligned.m8n8.x4.trans.shared.b16 {%0,%1,%2,%3}, [%4];"
                 : "=r"(r[0]), "=r"(r[1]), "=r"(r[2]), "=r"(r[3]) : "r"(addr));
}
__device__ __forceinline__ void mma_bf16(float* d, const uint32_t* a, uint32_t b0, uint32_t b1) {
    asm volatile(
        "mma.sync.aligned.m16n8k16.row.col.f32.bf16.bf16.f32 "
        "{%0,%1,%2,%3}, {%4,%5,%6,%7}, {%8,%9}, {%0,%1,%2,%3};"
        : "+f"(d[0]), "+f"(d[1]), "+f"(d[2]), "+f"(d[3])
        : "r"(a[0]), "r"(a[1]), "r"(a[2]), "r"(a[3]), "r"(b0), "r"(b1));
}
// exp on the FMA pipe: 2^(x*log2e), deg-5 poly. rel err ~5e-7.
__device__ __forceinline__ float fast_exp(float x) {
    float y = fmaxf(x * 1.4426950408889634f, -100.0f);
    int n = __float2int_rn(y);
    float f = y - (float)n;
    float p = 1.3333558146e-3f;
    p = fmaf(p, f, 9.6181291076e-3f);
    p = fmaf(p, f, 5.5504108665e-2f);
    p = fmaf(p, f, 2.4022650696e-1f);
    p = fmaf(p, f, 6.9314718056e-1f);
    p = fmaf(p, f, 1.0f);
    return __int_as_float(__float_as_int(p) + (n << 23));
}
// split (a,b) fp32 pair -> bf16x2 hi + bf16x2 lo (lo = residual)
__device__ __forceinline__ void pack_split(float a, float b, uint32_t& hi2, uint32_t& lo2) {
    __nv_bfloat162 hb = __float22bfloat162_rn(make_float2(a, b));
    uint32_t h;
    memcpy(&h, &hb, 4);
    float ra = a - __uint_as_float(h << 16);
    float rb = b - __uint_as_float(h & 0xFFFF0000u);
    __nv_bfloat162 lb = __float22bfloat162_rn(make_float2(ra, rb));
    uint32_t l;
    memcpy(&l, &lb, 4);
    hi2 = h; lo2 = l;
}

// ---------------------------------------------------------------------------
// fp32 -> (bf16 hi, bf16 lo) split (inputs + weights only)
// ---------------------------------------------------------------------------
__global__ void split_kernel(const float* __restrict__ x, __nv_bfloat16* __restrict__ hi,
                             __nv_bfloat16* __restrict__ lo, int n)
{
    int i = (blockIdx.x * blockDim.x + threadIdx.x) * 4;
    if (i >= n) return;
    float4 v = *(const float4*)(x + i);
    uint32_t h0, l0, h1, l1;
    pack_split(v.x, v.y, h0, l0);
    pack_split(v.z, v.w, h1, l1);
    *(uint2*)(hi + i) = make_uint2(h0, h1);
    *(uint2*)(lo + i) = make_uint2(l0, l1);
}

// ---------------------------------------------------------------------------
// bf16-split GEMM via mma.sync — 3-stage pipeline, ONE barrier per chunk:
//   C = Ahi*Whi^T + Alo*Whi^T + Ahi*Wlo^T + bias
// Fused epilogue MODE: 0 = fp32+bias; 1 = bias+split; 2 = bias+RoPE+scale+split.
// ---------------------------------------------------------------------------
#define GEMM_SMEM 98304
#define NCHUNK 48

template <int MODE>
__global__ __launch_bounds__(256, 2)
void mma_gemm(const __nv_bfloat16* __restrict__ Ahi, const __nv_bfloat16* __restrict__ Alo,
              const __nv_bfloat16* __restrict__ Whi, const __nv_bfloat16* __restrict__ Wlo,
              const float* __restrict__ bias, float* __restrict__ C,
              __nv_bfloat16* __restrict__ Oh, __nv_bfloat16* __restrict__ Ol,
              int L, int posStride, float scale)
{
    extern __shared__ char smc[];
    const uint32_t sbase = smem_u32(smc);
    const int tid = threadIdx.x;
    const int lane = tid & 31;
    const int wid = tid >> 5;
    const int warp_m = wid & 3;
    const int warp_n = wid >> 2;
    const int m0 = blockIdx.y * 128;
    const int n0 = blockIdx.x * 128;

    const int lc = tid & 7;
    const int lr = tid >> 3;

    float acc[2][8][4];
#pragma unroll
    for (int mi = 0; mi < 2; mi++)
#pragma unroll
        for (int ni = 0; ni < 8; ni++)
#pragma unroll
            for (int e = 0; e < 4; e++) acc[mi][ni][e] = 0.f;

    auto issue_load = [&](int ci) {
        const int seg = ci >> 4;
        const int kk = (ci & 15) << 6;
        const __nv_bfloat16* As = (seg == 1) ? Alo : Ahi;
        const __nv_bfloat16* Ws = (seg == 2) ? Wlo : Whi;
        const uint32_t st = (uint32_t)(ci % 3) * 32768u;
        const uint32_t da = sbase + st;
        const uint32_t db = sbase + st + 16384u;
        const uint32_t sw = ((uint32_t)(lc ^ (lr & 7))) << 4;
#pragma unroll
        for (int p = 0; p < 4; p++) {
            const int r = lr + p * 32;
            const uint32_t so = (uint32_t)(r * 128) + sw;
            cp16(da + so, As + (size_t)(m0 + r) * DMODEL + kk + lc * 8);
            cp16(db + so, Ws + (size_t)(n0 + r) * DMODEL + kk + lc * 8);
        }
    };

    issue_load(0);
    cp_commit();
    issue_load(1);
    cp_commit();

    for (int i = 0; i < NCHUNK; i++) {
        if (i + 1 < NCHUNK) cp_wait1(); else cp_wait0();
        __syncthreads();    // buf[i] readable; all warps done reading buf[(i+2)%3]
        if (i + 2 < NCHUNK) {
            issue_load(i + 2);
            cp_commit();
        }

        const uint32_t st = (uint32_t)(i % 3) * 32768u;
        const uint32_t abase = sbase + st + (uint32_t)(warp_m * 32) * 128;
        const uint32_t bbase = sbase + st + 16384u + (uint32_t)(warp_n * 64) * 128;

#pragma unroll
        for (int ks = 0; ks < 4; ks++) {
            uint32_t afr[2][4];
#pragma unroll
            for (int mi = 0; mi < 2; mi++) {
                const int row = mi * 16 + (lane & 15);
                const int ch = ks * 2 + (lane >> 4);
                ldsm_x4(abase + (uint32_t)(row * 128) + (((uint32_t)(ch ^ (row & 7))) << 4),
                        afr[mi]);
            }
#pragma unroll
            for (int g = 0; g < 4; g++) {
                const int n = g * 16 + (lane & 7) + ((lane & 16) >> 1);
                const int ch = ks * 2 + ((lane >> 3) & 1);
                uint32_t bfr[4];
                ldsm_x4(bbase + (uint32_t)(n * 128) + (((uint32_t)(ch ^ (n & 7))) << 4), bfr);
#pragma unroll
                for (int mi = 0; mi < 2; mi++) {
                    mma_bf16(acc[mi][2 * g + 0], afr[mi], bfr[0], bfr[1]);
                    mma_bf16(acc[mi][2 * g + 1], afr[mi], bfr[2], bfr[3]);
                }
            }
        }
        // no trailing barrier: buf rotation + top-of-loop barrier covers WAR
    }

    // ---- fused epilogue ----
    const int colb = n0 + warp_n * 64 + (lane & 3) * 2;

    if (MODE == 0) {
#pragma unroll
        for (int mi = 0; mi < 2; mi++) {
            const int row = m0 + warp_m * 32 + mi * 16 + (lane >> 2);
#pragma unroll
            for (int ni = 0; ni < 8; ni++) {
                const int col = colb + ni * 8;
                const float bx = bias[col], by = bias[col + 1];
                *(float2*)&C[(size_t)row * DMODEL + col] =
                    make_float2(acc[mi][ni][0] + bx, acc[mi][ni][1] + by);
                *(float2*)&C[(size_t)(row + 8) * DMODEL + col] =
                    make_float2(acc[mi][ni][2] + bx, acc[mi][ni][3] + by);
            }
        }
    } else if (MODE == 1) {
#pragma unroll
        for (int mi = 0; mi < 2; mi++) {
            const int row = m0 + warp_m * 32 + mi * 16 + (lane >> 2);
#pragma unroll
            for (int ni = 0; ni < 8; ni++) {
                const int col = colb + ni * 8;
                const float bx = bias[col], by = bias[col + 1];
                uint32_t h2, l2;
                pack_split(acc[mi][ni][0] + bx, acc[mi][ni][1] + by, h2, l2);
                *(uint32_t*)&Oh[(size_t)row * DMODEL + col] = h2;
                *(uint32_t*)&Ol[(size_t)row * DMODEL + col] = l2;
                pack_split(acc[mi][ni][2] + bx, acc[mi][ni][3] + by, h2, l2);
                *(uint32_t*)&Oh[(size_t)(row + 8) * DMODEL + col] = h2;
                *(uint32_t*)&Ol[(size_t)(row + 8) * DMODEL + col] = l2;
            }
        }
    } else {
        // MODE 2: RoPE pairs (j, j+32) are (ni, ni+4) — register-local.
#pragma unroll
        for (int mi = 0; mi < 2; mi++) {
#pragma unroll
            for (int half = 0; half < 2; half++) {
                const int row = m0 + warp_m * 32 + mi * 16 + (lane >> 2) + half * 8;
                const int eo = half * 2;
                const float pos = (float)((row % L) * posStride);
#pragma unroll
                for (int nj = 0; nj < 4; nj++) {
                    const int col = colb + nj * 8;
                    float y1[2], y2[2];
#pragma unroll
                    for (int el = 0; el < 2; el++) {
                        const int j32 = nj * 8 + (lane & 3) * 2 + el;
                        const float invf =
                            1.0f / powf(10000.0f, (float)j32 * (1.0f / 32.0f));
                        float s, c;
                        sincosf(pos * invf, &s, &c);
                        const float x1 = acc[mi][nj][eo + el] + bias[col + el];
                        const float x2 = acc[mi][nj + 4][eo + el] + bias[col + 32 + el];
                        y1[el] = (x1 * c - x2 * s) * scale;
                        y2[el] = (x2 * c + x1 * s) * scale;
                    }
                    uint32_t h2, l2;
                    pack_split(y1[0], y1[1], h2, l2);
                    *(uint32_t*)&Oh[(size_t)row * DMODEL + col] = h2;
                    *(uint32_t*)&Ol[(size_t)row * DMODEL + col] = l2;
                    pack_split(y2[0], y2[1], h2, l2);
                    *(uint32_t*)&Oh[(size_t)row * DMODEL + col + 32] = h2;
                    *(uint32_t*)&Ol[(size_t)row * DMODEL + col + 32] = l2;
                }
            }
        }
    }
}

// ---------------------------------------------------------------------------
// Tensor-core flash attention — 3-stage KV pipeline, ONE barrier per chunk.
//  smem = 112KB: [Qlo 16KB persistent | 3 x 32KB KV stages]
//  stage: KH @0, KL @8K, VH @16K, VL @24K. Q-hi staged transiently in stage0.
// ---------------------------------------------------------------------------
#define ATTN_SMEM 114688
#define NKCH (SK / 64)

__global__ __launch_bounds__(256, 2)
void attn_mma(const __nv_bfloat16* __restrict__ Qh, const __nv_bfloat16* __restrict__ Ql,
              const __nv_bfloat16* __restrict__ Kh, const __nv_bfloat16* __restrict__ Kl,
              const __nv_bfloat16* __restrict__ Vh, const __nv_bfloat16* __restrict__ Vl,
              __nv_bfloat16* __restrict__ Oh, __nv_bfloat16* __restrict__ Ol)
{
    extern __shared__ char smc[];
    const uint32_t sbase = smem_u32(smc);
    const int tid = threadIdx.x;
    const int lane = tid & 31;
    const int wid = tid >> 5;
    const int b = blockIdx.z;
    const int h = blockIdx.y;
    const int s0 = blockIdx.x * 128;

    const uint32_t QLS = 0;            // persistent Q-lo (16KB)
    const uint32_t STG0 = 16384;       // 3 x 32KB stages

    // ---- Phase 0: Q hi -> stage0 (transient), Q lo -> QLS (persistent) ----
    {
        const int r = tid >> 1;
        const int cb = (tid & 1) * 4;
        const size_t src = ((size_t)(b * SQ + s0 + r)) * DMODEL + h * HD;
#pragma unroll
        for (int u = 0; u < 4; u++) {
            const int c = cb + u;
            const uint32_t off = (uint32_t)(r * 128) + (((uint32_t)(c ^ (r & 7))) << 4);
            cp16(sbase + STG0 + off, Qh + src + c * 8);
            cp16(sbase + QLS + off, Ql + src + c * 8);
        }
    }
    cp_commit();
    cp_wait0();
    __syncthreads();

    uint32_t qfh[4][4];
    {
        const int row = wid * 16 + (lane & 15);
#pragma unroll
        for (int ks = 0; ks < 4; ks++) {
            const int ch = ks * 2 + (lane >> 4);
            const uint32_t off = (uint32_t)(row * 128) + (((uint32_t)(ch ^ (row & 7))) << 4);
            ldsm_x4(sbase + STG0 + off, qfh[ks]);
        }
    }
    __syncthreads();   // all warps done reading Q-hi before chunk0 overwrites stage0

    auto issue_kv = [&](int ci) {
        const uint32_t st = STG0 + (uint32_t)(ci % 3) * 32768u;
        const int r = tid >> 2;
        const int cb = (tid & 3) * 2;
        const size_t src = ((size_t)(b * SK + ci * 64 + r)) * DMODEL + h * HD;
#pragma unroll
        for (int u = 0; u < 2; u++) {
            const int c = cb + u;
            const uint32_t off = (uint32_t)(r * 128) + (((uint32_t)(c ^ (r & 7))) << 4);
            cp16(st + sbase + off, Kh + src + c * 8);
            cp16(st + sbase + 8192u + off, Kl + src + c * 8);
            cp16(st + sbase + 16384u + off, Vh + src + c * 8);
            cp16(st + sbase + 24576u + off, Vl + src + c * 8);
        }
    };

    issue_kv(0);
    cp_commit();
    issue_kv(1);
    cp_commit();

    float oacc[8][4];
#pragma unroll
    for (int g = 0; g < 8; g++)
#pragma unroll
        for (int e = 0; e < 4; e++) oacc[g][e] = 0.f;
    float m0 = -INFINITY, m1 = -INFINITY, l0 = 0.f, l1 = 0.f;

    const int qrow = wid * 16 + (lane & 15);

    for (int i = 0; i < NKCH; i++) {
        if (i + 1 < NKCH) cp_wait1(); else cp_wait0();
        __syncthreads();   // buf[i] readable; all warps done with buf[(i+2)%3]
        if (i + 2 < NKCH) {
            issue_kv(i + 2);
            cp_commit();
        }

        const uint32_t st = sbase + STG0 + (uint32_t)(i % 3) * 32768u;
        const uint32_t kh = st, kl = st + 8192u;
        const uint32_t vh = st + 16384u, vl = st + 24576u;

        float sacc[8][4];
#pragma unroll
        for (int g = 0; g < 8; g++)
#pragma unroll
            for (int e = 0; e < 4; e++) sacc[g][e] = 0.f;

#pragma unroll
        for (int ks = 0; ks < 4; ks++) {
            uint32_t qfl[4];
            {
                const int ch = ks * 2 + (lane >> 4);
                const uint32_t off =
                    (uint32_t)(qrow * 128) + (((uint32_t)(ch ^ (qrow & 7))) << 4);
                ldsm_x4(sbase + QLS + off, qfl);
            }
#pragma unroll
            for (int g = 0; g < 4; g++) {
                const int n = g * 16 + (lane & 7) + ((lane & 16) >> 1);
                const int ch = ks * 2 + ((lane >> 3) & 1);
                const uint32_t off = (uint32_t)(n * 128) + (((uint32_t)(ch ^ (n & 7))) << 4);
                uint32_t bh[4], bl[4];
                ldsm_x4(kh + off, bh);
                ldsm_x4(kl + off, bl);
                mma_bf16(sacc[2 * g + 0], qfh[ks], bh[0], bh[1]);
                mma_bf16(sacc[2 * g + 0], qfl, bh[0], bh[1]);
                mma_bf16(sacc[2 * g + 0], qfh[ks], bl[0], bl[1]);
                mma_bf16(sacc[2 * g + 1], qfh[ks], bh[2], bh[3]);
                mma_bf16(sacc[2 * g + 1], qfl, bh[2], bh[3]);
                mma_bf16(sacc[2 * g + 1], qfh[ks], bl[2], bl[3]);
            }
        }

        float mx0 = sacc[0][0], mx1 = sacc[0][2];
#pragma unroll
        for (int g = 0; g < 8; g++) {
            mx0 = fmaxf(mx0, fmaxf(sacc[g][0], sacc[g][1]));
            mx1 = fmaxf(mx1, fmaxf(sacc[g][2], sacc[g][3]));
        }
        mx0 = fmaxf(mx0, __shfl_xor_sync(0xffffffffu, mx0, 1));
        mx0 = fmaxf(mx0, __shfl_xor_sync(0xffffffffu, mx0, 2));
        mx1 = fmaxf(mx1, __shfl_xor_sync(0xffffffffu, mx1, 1));
        mx1 = fmaxf(mx1, __shfl_xor_sync(0xffffffffu, mx1, 2));
        const float mn0 = fmaxf(m0, mx0);
        const float mn1 = fmaxf(m1, mx1);
        const float a0 = fast_exp(m0 - mn0);
        const float a1 = fast_exp(m1 - mn1);
        m0 = mn0; m1 = mn1;
        float s0s = 0.f, s1s = 0.f;
#pragma unroll
        for (int g = 0; g < 8; g++) {
            sacc[g][0] = fast_exp(sacc[g][0] - mn0);
            sacc[g][1] = fast_exp(sacc[g][1] - mn0);
            sacc[g][2] = fast_exp(sacc[g][2] - mn1);
            sacc[g][3] = fast_exp(sacc[g][3] - mn1);
            s0s += sacc[g][0] + sacc[g][1];
            s1s += sacc[g][2] + sacc[g][3];
        }
        l0 = l0 * a0 + s0s;
        l1 = l1 * a1 + s1s;
#pragma unroll
        for (int g = 0; g < 8; g++) {
            oacc[g][0] *= a0; oacc[g][1] *= a0;
            oacc[g][2] *= a1; oacc[g][3] *= a1;
        }

#pragma unroll
        for (int ks = 0; ks < 4; ks++) {
            uint32_t ah[4], al[4];
            pack_split(sacc[2 * ks][0],     sacc[2 * ks][1],     ah[0], al[0]);
            pack_split(sacc[2 * ks][2],     sacc[2 * ks][3],     ah[1], al[1]);
            pack_split(sacc[2 * ks + 1][0], sacc[2 * ks + 1][1], ah[2], al[2]);
            pack_split(sacc[2 * ks + 1][2], sacc[2 * ks + 1][3], ah[3], al[3]);
            const int tile2 = lane >> 3;
            const int key = ks * 16 + (tile2 & 1) * 8 + (lane & 7);
#pragma unroll
            for (int g = 0; g < 4; g++) {
                const int c = g * 2 + (tile2 >> 1);
                const uint32_t off = (uint32_t)(key * 128) + (((uint32_t)(c ^ (key & 7))) << 4);
                uint32_t bh[4], bl[4];
                ldsm_x4t(vh + off, bh);
                ldsm_x4t(vl + off, bl);
                mma_bf16(oacc[2 * g + 0], ah, bh[0], bh[1]);
                mma_bf16(oacc[2 * g + 0], al, bh[0], bh[1]);
                mma_bf16(oacc[2 * g + 0], ah, bl[0], bl[1]);
                mma_bf16(oacc[2 * g + 1], ah, bh[2], bh[3]);
                mma_bf16(oacc[2 * g + 1], al, bh[2], bh[3]);
                mma_bf16(oacc[2 * g + 1], ah, bl[2], bl[3]);
            }
        }
        // no trailing barrier (3-stage rotation)
    }

    l0 += __shfl_xor_sync(0xffffffffu, l0, 1);
    l0 += __shfl_xor_sync(0xffffffffu, l0, 2);
    l1 += __shfl_xor_sync(0xffffffffu, l1, 1);
    l1 += __shfl_xor_sync(0xffffffffu, l1, 2);
    const float inv0 = 1.0f / l0;
    const float inv1 = 1.0f / l1;
    const int r0 = s0 + wid * 16 + (lane >> 2);
#pragma unroll
    for (int g = 0; g < 8; g++) {
        const int col = h * HD + g * 8 + (lane & 3) * 2;
        uint32_t h2, l2;
        pack_split(oacc[g][0] * inv0, oacc[g][1] * inv0, h2, l2);
        *(uint32_t*)&Oh[((size_t)(b * SQ) + r0) * DMODEL + col] = h2;
        *(uint32_t*)&Ol[((size_t)(b * SQ) + r0) * DMODEL + col] = l2;
        pack_split(oacc[g][2] * inv1, oacc[g][3] * inv1, h2, l2);
        *(uint32_t*)&Oh[((size_t)(b * SQ) + r0 + 8) * DMODEL + col] = h2;
        *(uint32_t*)&Ol[((size_t)(b * SQ) + r0 + 8) * DMODEL + col] = l2;
    }
}

// ---------------------------------------------------------------------------
extern "C" void kernel_launch(void* const* d_in, const int* in_sizes, int n_in,
                              void* d_out, int out_size)
{
    const float* query = (const float*)d_in[0];
    const float* kv    = (const float*)d_in[1];
    const float* q_w   = (const float*)d_in[2];
    const float* q_b   = (const float*)d_in[3];
    const float* k_w   = (const float*)d_in[4];
    const float* k_b   = (const float*)d_in[5];
    const float* v_w   = (const float*)d_in[6];
    const float* v_b   = (const float*)d_in[7];
    const float* out_w = (const float*)d_in[8];
    const float* out_b = (const float*)d_in[9];
    float* out = (float*)d_out;

    __nv_bfloat16 *qh, *ql, *kvh, *kvl, *oh, *ol;
    __nv_bfloat16 *wqh, *wql, *wkh, *wkl, *wvh, *wvl, *woh, *wol;
    __nv_bfloat16 *aqh, *aql, *akh, *akl, *avh, *avl;
    cudaGetSymbolAddress((void**)&qh,  g_qh);  cudaGetSymbolAddress((void**)&ql,  g_ql);
    cudaGetSymbolAddress((void**)&kvh, g_kvh); cudaGetSymbolAddress((void**)&kvl, g_kvl);
    cudaGetSymbolAddress((void**)&oh,  g_oh);  cudaGetSymbolAddress((void**)&ol,  g_ol);
    cudaGetSymbolAddress((void**)&wqh, g_wqh); cudaGetSymbolAddress((void**)&wql, g_wql);
    cudaGetSymbolAddress((void**)&wkh, g_wkh); cudaGetSymbolAddress((void**)&wkl, g_wkl);
    cudaGetSymbolAddress((void**)&wvh, g_wvh); cudaGetSymbolAddress((void**)&wvl, g_wvl);
    cudaGetSymbolAddress((void**)&woh, g_woh); cudaGetSymbolAddress((void**)&wol, g_wol);
    cudaGetSymbolAddress((void**)&aqh, g_aqh); cudaGetSymbolAddress((void**)&aql, g_aql);
    cudaGetSymbolAddress((void**)&akh, g_akh); cudaGetSymbolAddress((void**)&akl, g_akl);
    cudaGetSymbolAddress((void**)&avh, g_avh); cudaGetSymbolAddress((void**)&avl, g_avl);

    const int NQ = NB * SQ * DMODEL;
    const int NK = NB * SK * DMODEL;
    const int NW = DMODEL * DMODEL;

    // input + weight hi/lo splits
    split_kernel<<<NQ / 1024, 256>>>(query, qh, ql, NQ);
    split_kernel<<<NK / 1024, 256>>>(kv, kvh, kvl, NK);
    split_kernel<<<NW / 1024, 256>>>(q_w, wqh, wql, NW);
    split_kernel<<<NW / 1024, 256>>>(k_w, wkh, wkl, NW);
    split_kernel<<<NW / 1024, 256>>>(v_w, wvh, wvl, NW);
    split_kernel<<<NW / 1024, 256>>>(out_w, woh, wol, NW);

    // projections with fused epilogues (RoPE+split for Q/K, split for V)
    cudaFuncSetAttribute(mma_gemm<0>, cudaFuncAttributeMaxDynamicSharedMemorySize, GEMM_SMEM);
    cudaFuncSetAttribute(mma_gemm<1>, cudaFuncAttributeMaxDynamicSharedMemorySize, GEMM_SMEM);
    cudaFuncSetAttribute(mma_gemm<2>, cudaFuncAttributeMaxDynamicSharedMemorySize, GEMM_SMEM);
    mma_gemm<2><<<dim3(8, 32), 256, GEMM_SMEM>>>(qh, ql, wqh, wql, q_b, nullptr,
                                                 aqh, aql, SQ, 2, 0.125f);
    mma_gemm<2><<<dim3(8, 64), 256, GEMM_SMEM>>>(kvh, kvl, wkh, wkl, k_b, nullptr,
                                                 akh, akl, SK, 1, 1.0f);
    mma_gemm<1><<<dim3(8, 64), 256, GEMM_SMEM>>>(kvh, kvl, wvh, wvl, v_b, nullptr,
                                                 avh, avl, 0, 0, 0.f);

    // tensor-core flash attention (3-stage pipeline), bf16-split output
    cudaFuncSetAttribute(attn_mma, cudaFuncAttributeMaxDynamicSharedMemorySize, ATTN_SMEM);
    attn_mma<<<dim3(SQ / 128, NHEAD, NB), 256, ATTN_SMEM>>>(aqh, aql, akh, akl, avh, avl, oh, ol);

    // output projection (fp32 out)
    mma_gemm<0><<<dim3(8, 32), 256, GEMM_SMEM>>>(oh, ol, woh, wol, out_b, out,
                                                 nullptr, nullptr, 0, 0, 0.f);
}

// round 11
// speedup vs baseline: 1.0244x; 1.0244x over previous
#include <cuda_runtime.h>
#include <cuda_bf16.h>
#include <math.h>
#include <stdint.h>

#define DMODEL 1024
#define NHEAD  16
#define HD     64
#define NB     4
#define SQ     1024
#define SK     2048

// ---------------------------------------------------------------------------
// Scratch (__device__ globals: allocation-free rule)
// ---------------------------------------------------------------------------
__device__ __nv_bfloat16 g_qh[NB * SQ * DMODEL];
__device__ __nv_bfloat16 g_ql[NB * SQ * DMODEL];
__device__ __nv_bfloat16 g_kvh[NB * SK * DMODEL];
__device__ __nv_bfloat16 g_kvl[NB * SK * DMODEL];
__device__ __nv_bfloat16 g_oh[NB * SQ * DMODEL];
__device__ __nv_bfloat16 g_ol[NB * SQ * DMODEL];
__device__ __nv_bfloat16 g_wqh[DMODEL * DMODEL];
__device__ __nv_bfloat16 g_wql[DMODEL * DMODEL];
__device__ __nv_bfloat16 g_wkh[DMODEL * DMODEL];
__device__ __nv_bfloat16 g_wkl[DMODEL * DMODEL];
__device__ __nv_bfloat16 g_wvh[DMODEL * DMODEL];
__device__ __nv_bfloat16 g_wvl[DMODEL * DMODEL];
__device__ __nv_bfloat16 g_woh[DMODEL * DMODEL];
__device__ __nv_bfloat16 g_wol[DMODEL * DMODEL];

// attention operands (bf16 hi/lo, post-RoPE, written by fused gemm epilogues)
__device__ __nv_bfloat16 g_aqh[NB * SQ * DMODEL];
__device__ __nv_bfloat16 g_aql[NB * SQ * DMODEL];
__device__ __nv_bfloat16 g_akh[NB * SK * DMODEL];
__device__ __nv_bfloat16 g_akl[NB * SK * DMODEL];
__device__ __nv_bfloat16 g_avh[NB * SK * DMODEL];
__device__ __nv_bfloat16 g_avl[NB * SK * DMODEL];

// ---------------------------------------------------------------------------
// Helpers
// ---------------------------------------------------------------------------
__device__ __forceinline__ uint32_t smem_u32(const void* p) {
    uint32_t a;
    asm("{ .reg .u64 t; cvta.to.shared.u64 t, %1; cvt.u32.u64 %0, t; }" : "=r"(a) : "l"(p));
    return a;
}
__device__ __forceinline__ void cp16(uint32_t dst, const void* src) {
    asm volatile("cp.async.cg.shared.global [%0], [%1], 16;" :: "r"(dst), "l"(src));
}
__device__ __forceinline__ void cp_commit() {
    asm volatile("cp.async.commit_group;" ::: "memory");
}
__device__ __forceinline__ void cp_wait1() {
    asm volatile("cp.async.wait_group 1;" ::: "memory");
}
__device__ __forceinline__ void cp_wait0() {
    asm volatile("cp.async.wait_group 0;" ::: "memory");
}
__device__ __forceinline__ void ldsm_x4(uint32_t addr, uint32_t* r) {
    asm volatile("ldmatrix.sync.aligned.m8n8.x4.shared.b16 {%0,%1,%2,%3}, [%4];"
                 : "=r"(r[0]), "=r"(r[1]), "=r"(r[2]), "=r"(r[3]) : "r"(addr));
}
__device__ __forceinline__ void ldsm_x4t(uint32_t addr, uint32_t* r) {
    asm volatile("ldmatrix.sync.aligned.m8n8.x4.trans.shared.b16 {%0,%1,%2,%3}, [%4];"
                 : "=r"(r[0]), "=r"(r[1]), "=r"(r[2]), "=r"(r[3]) : "r"(addr));
}
__device__ __forceinline__ void mma_bf16(float* d, const uint32_t* a, uint32_t b0, uint32_t b1) {
    asm volatile(
        "mma.sync.aligned.m16n8k16.row.col.f32.bf16.bf16.f32 "
        "{%0,%1,%2,%3}, {%4,%5,%6,%7}, {%8,%9}, {%0,%1,%2,%3};"
        : "+f"(d[0]), "+f"(d[1]), "+f"(d[2]), "+f"(d[3])
        : "r"(a[0]), "r"(a[1]), "r"(a[2]), "r"(a[3]), "r"(b0), "r"(b1));
}
// exp on the FMA pipe: 2^(x*log2e), deg-5 poly. rel err ~5e-7.
__device__ __forceinline__ float fast_exp(float x) {
    float y = fmaxf(x * 1.4426950408889634f, -100.0f);
    int n = __float2int_rn(y);
    float f = y - (float)n;
    float p = 1.3333558146e-3f;
    p = fmaf(p, f, 9.6181291076e-3f);
    p = fmaf(p, f, 5.5504108665e-2f);
    p = fmaf(p, f, 2.4022650696e-1f);
    p = fmaf(p, f, 6.9314718056e-1f);
    p = fmaf(p, f, 1.0f);
    return __int_as_float(__float_as_int(p) + (n << 23));
}
// split (a,b) fp32 pair -> bf16x2 hi + bf16x2 lo (lo = residual)
__device__ __forceinline__ void pack_split(float a, float b, uint32_t& hi2, uint32_t& lo2) {
    __nv_bfloat162 hb = __float22bfloat162_rn(make_float2(a, b));
    uint32_t h;
    memcpy(&h, &hb, 4);
    float ra = a - __uint_as_float(h << 16);
    float rb = b - __uint_as_float(h & 0xFFFF0000u);
    __nv_bfloat162 lb = __float22bfloat162_rn(make_float2(ra, rb));
    uint32_t l;
    memcpy(&l, &lb, 4);
    hi2 = h; lo2 = l;
}

// ---------------------------------------------------------------------------
// fp32 -> (bf16 hi, bf16 lo) split for ONE array
// ---------------------------------------------------------------------------
__global__ void split_kernel(const float* __restrict__ x, __nv_bfloat16* __restrict__ hi,
                             __nv_bfloat16* __restrict__ lo, int n)
{
    int i = (blockIdx.x * blockDim.x + threadIdx.x) * 4;
    if (i >= n) return;
    float4 v = *(const float4*)(x + i);
    uint32_t h0, l0, h1, l1;
    pack_split(v.x, v.y, h0, l0);
    pack_split(v.z, v.w, h1, l1);
    *(uint2*)(hi + i) = make_uint2(h0, h1);
    *(uint2*)(lo + i) = make_uint2(l0, l1);
}

// Fused split of the 4 weight matrices (blockIdx.y selects). 1 launch instead of 4.
__global__ void split4_kernel(const float* __restrict__ s0, const float* __restrict__ s1,
                              const float* __restrict__ s2, const float* __restrict__ s3,
                              __nv_bfloat16* __restrict__ h0p, __nv_bfloat16* __restrict__ h1p,
                              __nv_bfloat16* __restrict__ h2p, __nv_bfloat16* __restrict__ h3p,
                              __nv_bfloat16* __restrict__ l0p, __nv_bfloat16* __restrict__ l1p,
                              __nv_bfloat16* __restrict__ l2p, __nv_bfloat16* __restrict__ l3p,
                              int n)
{
    const float* src;
    __nv_bfloat16 *hi, *lo;
    switch (blockIdx.y) {
        case 0: src = s0; hi = h0p; lo = l0p; break;
        case 1: src = s1; hi = h1p; lo = l1p; break;
        case 2: src = s2; hi = h2p; lo = l2p; break;
        default: src = s3; hi = h3p; lo = l3p; break;
    }
    int i = (blockIdx.x * blockDim.x + threadIdx.x) * 4;
    if (i >= n) return;
    float4 v = *(const float4*)(src + i);
    uint32_t ha, la, hb, lb;
    pack_split(v.x, v.y, ha, la);
    pack_split(v.z, v.w, hb, lb);
    *(uint2*)(hi + i) = make_uint2(ha, hb);
    *(uint2*)(lo + i) = make_uint2(la, lb);
}

// ---------------------------------------------------------------------------
// bf16-split GEMM via mma.sync — R8-validated 2-stage mainloop:
//   C = Ahi*Whi^T + Alo*Whi^T + Ahi*Wlo^T + bias
// 128x128 CTA tile, BK=64, 48 chunks (3 segments x 16), double buffer.
// Fused epilogue MODE: 0 = fp32+bias; 1 = bias+split; 2 = bias+RoPE+scale+split.
// ---------------------------------------------------------------------------
#define GEMM_SMEM 65536
#define NCHUNK 48

template <int MODE>
__global__ __launch_bounds__(256, 2)
void mma_gemm(const __nv_bfloat16* __restrict__ Ahi, const __nv_bfloat16* __restrict__ Alo,
              const __nv_bfloat16* __restrict__ Whi, const __nv_bfloat16* __restrict__ Wlo,
              const float* __restrict__ bias, float* __restrict__ C,
              __nv_bfloat16* __restrict__ Oh, __nv_bfloat16* __restrict__ Ol,
              int L, int posStride, float scale)
{
    extern __shared__ char smc[];
    const uint32_t sbase = smem_u32(smc);
    const int tid = threadIdx.x;
    const int lane = tid & 31;
    const int wid = tid >> 5;
    const int warp_m = wid & 3;
    const int warp_n = wid >> 2;
    const int m0 = blockIdx.y * 128;
    const int n0 = blockIdx.x * 128;

    const int lc = tid & 7;
    const int lr = tid >> 3;

    float acc[2][8][4];
#pragma unroll
    for (int mi = 0; mi < 2; mi++)
#pragma unroll
        for (int ni = 0; ni < 8; ni++)
#pragma unroll
            for (int e = 0; e < 4; e++) acc[mi][ni][e] = 0.f;

    auto issue_load = [&](int ci) {
        const int seg = ci >> 4;
        const int kk = (ci & 15) << 6;
        const __nv_bfloat16* As = (seg == 1) ? Alo : Ahi;
        const __nv_bfloat16* Ws = (seg == 2) ? Wlo : Whi;
        const uint32_t aoff = (ci & 1) ? 32768u : 0u;
        const uint32_t da = sbase + aoff;
        const uint32_t db = sbase + aoff + 16384u;
        const uint32_t sw = ((uint32_t)(lc ^ (lr & 7))) << 4;
#pragma unroll
        for (int p = 0; p < 4; p++) {
            const int r = lr + p * 32;
            const uint32_t so = (uint32_t)(r * 128) + sw;
            cp16(da + so, As + (size_t)(m0 + r) * DMODEL + kk + lc * 8);
            cp16(db + so, Ws + (size_t)(n0 + r) * DMODEL + kk + lc * 8);
        }
    };

    issue_load(0);
    cp_commit();

    for (int i = 0; i < NCHUNK; i++) {
        if (i + 1 < NCHUNK) {
            issue_load(i + 1);
            cp_commit();
            cp_wait1();
        } else {
            cp_wait0();
        }
        __syncthreads();

        const uint32_t aoff = (i & 1) ? 32768u : 0u;
        const uint32_t abase = sbase + aoff + (uint32_t)(warp_m * 32) * 128;
        const uint32_t bbase = sbase + aoff + 16384u + (uint32_t)(warp_n * 64) * 128;

#pragma unroll
        for (int ks = 0; ks < 4; ks++) {
            uint32_t afr[2][4];
#pragma unroll
            for (int mi = 0; mi < 2; mi++) {
                const int row = mi * 16 + (lane & 15);
                const int ch = ks * 2 + (lane >> 4);
                ldsm_x4(abase + (uint32_t)(row * 128) + (((uint32_t)(ch ^ (row & 7))) << 4),
                        afr[mi]);
            }
#pragma unroll
            for (int g = 0; g < 4; g++) {
                const int n = g * 16 + (lane & 7) + ((lane & 16) >> 1);
                const int ch = ks * 2 + ((lane >> 3) & 1);
                uint32_t bfr[4];
                ldsm_x4(bbase + (uint32_t)(n * 128) + (((uint32_t)(ch ^ (n & 7))) << 4), bfr);
#pragma unroll
                for (int mi = 0; mi < 2; mi++) {
                    mma_bf16(acc[mi][2 * g + 0], afr[mi], bfr[0], bfr[1]);
                    mma_bf16(acc[mi][2 * g + 1], afr[mi], bfr[2], bfr[3]);
                }
            }
        }
        __syncthreads();
    }

    // ---- fused epilogue ----
    const int colb = n0 + warp_n * 64 + (lane & 3) * 2;

    if (MODE == 0) {
#pragma unroll
        for (int mi = 0; mi < 2; mi++) {
            const int row = m0 + warp_m * 32 + mi * 16 + (lane >> 2);
#pragma unroll
            for (int ni = 0; ni < 8; ni++) {
                const int col = colb + ni * 8;
                const float bx = bias[col], by = bias[col + 1];
                *(float2*)&C[(size_t)row * DMODEL + col] =
                    make_float2(acc[mi][ni][0] + bx, acc[mi][ni][1] + by);
                *(float2*)&C[(size_t)(row + 8) * DMODEL + col] =
                    make_float2(acc[mi][ni][2] + bx, acc[mi][ni][3] + by);
            }
        }
    } else if (MODE == 1) {
#pragma unroll
        for (int mi = 0; mi < 2; mi++) {
            const int row = m0 + warp_m * 32 + mi * 16 + (lane >> 2);
#pragma unroll
            for (int ni = 0; ni < 8; ni++) {
                const int col = colb + ni * 8;
                const float bx = bias[col], by = bias[col + 1];
                uint32_t h2, l2;
                pack_split(acc[mi][ni][0] + bx, acc[mi][ni][1] + by, h2, l2);
                *(uint32_t*)&Oh[(size_t)row * DMODEL + col] = h2;
                *(uint32_t*)&Ol[(size_t)row * DMODEL + col] = l2;
                pack_split(acc[mi][ni][2] + bx, acc[mi][ni][3] + by, h2, l2);
                *(uint32_t*)&Oh[(size_t)(row + 8) * DMODEL + col] = h2;
                *(uint32_t*)&Ol[(size_t)(row + 8) * DMODEL + col] = l2;
            }
        }
    } else {
        // MODE 2: RoPE pairs (j, j+32) are (ni, ni+4) — register-local.
#pragma unroll
        for (int mi = 0; mi < 2; mi++) {
#pragma unroll
            for (int half = 0; half < 2; half++) {
                const int row = m0 + warp_m * 32 + mi * 16 + (lane >> 2) + half * 8;
                const int eo = half * 2;
                const float pos = (float)((row % L) * posStride);
#pragma unroll
                for (int nj = 0; nj < 4; nj++) {
                    const int col = colb + nj * 8;
                    float y1[2], y2[2];
#pragma unroll
                    for (int el = 0; el < 2; el++) {
                        const int j32 = nj * 8 + (lane & 3) * 2 + el;
                        const float invf =
                            1.0f / powf(10000.0f, (float)j32 * (1.0f / 32.0f));
                        float s, c;
                        sincosf(pos * invf, &s, &c);
                        const float x1 = acc[mi][nj][eo + el] + bias[col + el];
                        const float x2 = acc[mi][nj + 4][eo + el] + bias[col + 32 + el];
                        y1[el] = (x1 * c - x2 * s) * scale;
                        y2[el] = (x2 * c + x1 * s) * scale;
                    }
                    uint32_t h2, l2;
                    pack_split(y1[0], y1[1], h2, l2);
                    *(uint32_t*)&Oh[(size_t)row * DMODEL + col] = h2;
                    *(uint32_t*)&Ol[(size_t)row * DMODEL + col] = l2;
                    pack_split(y2[0], y2[1], h2, l2);
                    *(uint32_t*)&Oh[(size_t)row * DMODEL + col + 32] = h2;
                    *(uint32_t*)&Ol[(size_t)row * DMODEL + col + 32] = l2;
                }
            }
        }
    }
}

// ---------------------------------------------------------------------------
// Tensor-core flash attention — R8-validated: 2 CTAs/SM, 80KB smem,
// Qlo persistent (re-loaded per chunk), Qhi fragments in regs, 2-stage KV.
// ---------------------------------------------------------------------------
#define ATTN_SMEM 81920
#define NKCH (SK / 64)

__global__ __launch_bounds__(256, 2)
void attn_mma(const __nv_bfloat16* __restrict__ Qh, const __nv_bfloat16* __restrict__ Ql,
              const __nv_bfloat16* __restrict__ Kh, const __nv_bfloat16* __restrict__ Kl,
              const __nv_bfloat16* __restrict__ Vh, const __nv_bfloat16* __restrict__ Vl,
              __nv_bfloat16* __restrict__ Oh, __nv_bfloat16* __restrict__ Ol)
{
    extern __shared__ char smc[];
    const uint32_t sbase = smem_u32(smc);
    const int tid = threadIdx.x;
    const int lane = tid & 31;
    const int wid = tid >> 5;
    const int b = blockIdx.z;
    const int h = blockIdx.y;
    const int s0 = blockIdx.x * 128;

    const uint32_t QLS = 0;            // persistent Q-lo (16KB)
    const uint32_t STG0 = 16384;       // stage base (2 x 32KB)

    // ---- Phase 0: Q hi -> stage0 (transient), Q lo -> QLS (persistent) ----
    {
        const int r = tid >> 1;
        const int cb = (tid & 1) * 4;
        const size_t src = ((size_t)(b * SQ + s0 + r)) * DMODEL + h * HD;
#pragma unroll
        for (int u = 0; u < 4; u++) {
            const int c = cb + u;
            const uint32_t off = (uint32_t)(r * 128) + (((uint32_t)(c ^ (r & 7))) << 4);
            cp16(sbase + STG0 + off, Qh + src + c * 8);
            cp16(sbase + QLS + off, Ql + src + c * 8);
        }
    }
    cp_commit();
    cp_wait0();
    __syncthreads();

    uint32_t qfh[4][4];
    {
        const int row = wid * 16 + (lane & 15);
#pragma unroll
        for (int ks = 0; ks < 4; ks++) {
            const int ch = ks * 2 + (lane >> 4);
            const uint32_t off = (uint32_t)(row * 128) + (((uint32_t)(ch ^ (row & 7))) << 4);
            ldsm_x4(sbase + STG0 + off, qfh[ks]);
        }
    }
    __syncthreads();   // all warps done reading Q-hi before chunk0 overwrites stage0

    auto issue_kv = [&](int ci) {
        const uint32_t st = STG0 + (uint32_t)(ci & 1) * 32768u;
        const int r = tid >> 2;
        const int cb = (tid & 3) * 2;
        const size_t src = ((size_t)(b * SK + ci * 64 + r)) * DMODEL + h * HD;
#pragma unroll
        for (int u = 0; u < 2; u++) {
            const int c = cb + u;
            const uint32_t off = (uint32_t)(r * 128) + (((uint32_t)(c ^ (r & 7))) << 4);
            cp16(st + sbase + off, Kh + src + c * 8);
            cp16(st + sbase + 8192u + off, Kl + src + c * 8);
            cp16(st + sbase + 16384u + off, Vh + src + c * 8);
            cp16(st + sbase + 24576u + off, Vl + src + c * 8);
        }
    };

    issue_kv(0);
    cp_commit();

    float oacc[8][4];
#pragma unroll
    for (int g = 0; g < 8; g++)
#pragma unroll
        for (int e = 0; e < 4; e++) oacc[g][e] = 0.f;
    float m0 = -INFINITY, m1 = -INFINITY, l0 = 0.f, l1 = 0.f;

    const int qrow = wid * 16 + (lane & 15);

    for (int i = 0; i < NKCH; i++) {
        if (i + 1 < NKCH) {
            issue_kv(i + 1);
            cp_commit();
            cp_wait1();
        } else {
            cp_wait0();
        }
        __syncthreads();

        const uint32_t st = sbase + STG0 + (uint32_t)(i & 1) * 32768u;
        const uint32_t kh = st, kl = st + 8192u;
        const uint32_t vh = st + 16384u, vl = st + 24576u;

        float sacc[8][4];
#pragma unroll
        for (int g = 0; g < 8; g++)
#pragma unroll
            for (int e = 0; e < 4; e++) sacc[g][e] = 0.f;

#pragma unroll
        for (int ks = 0; ks < 4; ks++) {
            uint32_t qfl[4];
            {
                const int ch = ks * 2 + (lane >> 4);
                const uint32_t off =
                    (uint32_t)(qrow * 128) + (((uint32_t)(ch ^ (qrow & 7))) << 4);
                ldsm_x4(sbase + QLS + off, qfl);
            }
#pragma unroll
            for (int g = 0; g < 4; g++) {
                const int n = g * 16 + (lane & 7) + ((lane & 16) >> 1);
                const int ch = ks * 2 + ((lane >> 3) & 1);
                const uint32_t off = (uint32_t)(n * 128) + (((uint32_t)(ch ^ (n & 7))) << 4);
                uint32_t bh[4], bl[4];
                ldsm_x4(kh + off, bh);
                ldsm_x4(kl + off, bl);
                mma_bf16(sacc[2 * g + 0], qfh[ks], bh[0], bh[1]);
                mma_bf16(sacc[2 * g + 0], qfl, bh[0], bh[1]);
                mma_bf16(sacc[2 * g + 0], qfh[ks], bl[0], bl[1]);
                mma_bf16(sacc[2 * g + 1], qfh[ks], bh[2], bh[3]);
                mma_bf16(sacc[2 * g + 1], qfl, bh[2], bh[3]);
                mma_bf16(sacc[2 * g + 1], qfh[ks], bl[2], bl[3]);
            }
        }

        float mx0 = sacc[0][0], mx1 = sacc[0][2];
#pragma unroll
        for (int g = 0; g < 8; g++) {
            mx0 = fmaxf(mx0, fmaxf(sacc[g][0], sacc[g][1]));
            mx1 = fmaxf(mx1, fmaxf(sacc[g][2], sacc[g][3]));
        }
        mx0 = fmaxf(mx0, __shfl_xor_sync(0xffffffffu, mx0, 1));
        mx0 = fmaxf(mx0, __shfl_xor_sync(0xffffffffu, mx0, 2));
        mx1 = fmaxf(mx1, __shfl_xor_sync(0xffffffffu, mx1, 1));
        mx1 = fmaxf(mx1, __shfl_xor_sync(0xffffffffu, mx1, 2));
        const float mn0 = fmaxf(m0, mx0);
        const float mn1 = fmaxf(m1, mx1);
        const float a0 = fast_exp(m0 - mn0);
        const float a1 = fast_exp(m1 - mn1);
        m0 = mn0; m1 = mn1;
        float s0s = 0.f, s1s = 0.f;
#pragma unroll
        for (int g = 0; g < 8; g++) {
            sacc[g][0] = fast_exp(sacc[g][0] - mn0);
            sacc[g][1] = fast_exp(sacc[g][1] - mn0);
            sacc[g][2] = fast_exp(sacc[g][2] - mn1);
            sacc[g][3] = fast_exp(sacc[g][3] - mn1);
            s0s += sacc[g][0] + sacc[g][1];
            s1s += sacc[g][2] + sacc[g][3];
        }
        l0 = l0 * a0 + s0s;
        l1 = l1 * a1 + s1s;
#pragma unroll
        for (int g = 0; g < 8; g++) {
            oacc[g][0] *= a0; oacc[g][1] *= a0;
            oacc[g][2] *= a1; oacc[g][3] *= a1;
        }

#pragma unroll
        for (int ks = 0; ks < 4; ks++) {
            uint32_t ah[4], al[4];
            pack_split(sacc[2 * ks][0],     sacc[2 * ks][1],     ah[0], al[0]);
            pack_split(sacc[2 * ks][2],     sacc[2 * ks][3],     ah[1], al[1]);
            pack_split(sacc[2 * ks + 1][0], sacc[2 * ks + 1][1], ah[2], al[2]);
            pack_split(sacc[2 * ks + 1][2], sacc[2 * ks + 1][3], ah[3], al[3]);
            const int tile2 = lane >> 3;
            const int key = ks * 16 + (tile2 & 1) * 8 + (lane & 7);
#pragma unroll
            for (int g = 0; g < 4; g++) {
                const int c = g * 2 + (tile2 >> 1);
                const uint32_t off = (uint32_t)(key * 128) + (((uint32_t)(c ^ (key & 7))) << 4);
                uint32_t bh[4], bl[4];
                ldsm_x4t(vh + off, bh);
                ldsm_x4t(vl + off, bl);
                mma_bf16(oacc[2 * g + 0], ah, bh[0], bh[1]);
                mma_bf16(oacc[2 * g + 0], al, bh[0], bh[1]);
                mma_bf16(oacc[2 * g + 0], ah, bl[0], bl[1]);
                mma_bf16(oacc[2 * g + 1], ah, bh[2], bh[3]);
                mma_bf16(oacc[2 * g + 1], al, bh[2], bh[3]);
                mma_bf16(oacc[2 * g + 1], ah, bl[2], bl[3]);
            }
        }
        __syncthreads();
    }

    l0 += __shfl_xor_sync(0xffffffffu, l0, 1);
    l0 += __shfl_xor_sync(0xffffffffu, l0, 2);
    l1 += __shfl_xor_sync(0xffffffffu, l1, 1);
    l1 += __shfl_xor_sync(0xffffffffu, l1, 2);
    const float inv0 = 1.0f / l0;
    const float inv1 = 1.0f / l1;
    const int r0 = s0 + wid * 16 + (lane >> 2);
#pragma unroll
    for (int g = 0; g < 8; g++) {
        const int col = h * HD + g * 8 + (lane & 3) * 2;
        uint32_t h2, l2;
        pack_split(oacc[g][0] * inv0, oacc[g][1] * inv0, h2, l2);
        *(uint32_t*)&Oh[((size_t)(b * SQ) + r0) * DMODEL + col] = h2;
        *(uint32_t*)&Ol[((size_t)(b * SQ) + r0) * DMODEL + col] = l2;
        pack_split(oacc[g][2] * inv1, oacc[g][3] * inv1, h2, l2);
        *(uint32_t*)&Oh[((size_t)(b * SQ) + r0 + 8) * DMODEL + col] = h2;
        *(uint32_t*)&Ol[((size_t)(b * SQ) + r0 + 8) * DMODEL + col] = l2;
    }
}

// ---------------------------------------------------------------------------
extern "C" void kernel_launch(void* const* d_in, const int* in_sizes, int n_in,
                              void* d_out, int out_size)
{
    const float* query = (const float*)d_in[0];
    const float* kv    = (const float*)d_in[1];
    const float* q_w   = (const float*)d_in[2];
    const float* q_b   = (const float*)d_in[3];
    const float* k_w   = (const float*)d_in[4];
    const float* k_b   = (const float*)d_in[5];
    const float* v_w   = (const float*)d_in[6];
    const float* v_b   = (const float*)d_in[7];
    const float* out_w = (const float*)d_in[8];
    const float* out_b = (const float*)d_in[9];
    float* out = (float*)d_out;

    __nv_bfloat16 *qh, *ql, *kvh, *kvl, *oh, *ol;
    __nv_bfloat16 *wqh, *wql, *wkh, *wkl, *wvh, *wvl, *woh, *wol;
    __nv_bfloat16 *aqh, *aql, *akh, *akl, *avh, *avl;
    cudaGetSymbolAddress((void**)&qh,  g_qh);  cudaGetSymbolAddress((void**)&ql,  g_ql);
    cudaGetSymbolAddress((void**)&kvh, g_kvh); cudaGetSymbolAddress((void**)&kvl, g_kvl);
    cudaGetSymbolAddress((void**)&oh,  g_oh);  cudaGetSymbolAddress((void**)&ol,  g_ol);
    cudaGetSymbolAddress((void**)&wqh, g_wqh); cudaGetSymbolAddress((void**)&wql, g_wql);
    cudaGetSymbolAddress((void**)&wkh, g_wkh); cudaGetSymbolAddress((void**)&wkl, g_wkl);
    cudaGetSymbolAddress((void**)&wvh, g_wvh); cudaGetSymbolAddress((void**)&wvl, g_wvl);
    cudaGetSymbolAddress((void**)&woh, g_woh); cudaGetSymbolAddress((void**)&wol, g_wol);
    cudaGetSymbolAddress((void**)&aqh, g_aqh); cudaGetSymbolAddress((void**)&aql, g_aql);
    cudaGetSymbolAddress((void**)&akh, g_akh); cudaGetSymbolAddress((void**)&akl, g_akl);
    cudaGetSymbolAddress((void**)&avh, g_avh); cudaGetSymbolAddress((void**)&avl, g_avl);

    const int NQ = NB * SQ * DMODEL;
    const int NK = NB * SK * DMODEL;
    const int NW = DMODEL * DMODEL;

    // launch 0: all 4 weight splits fused; launch 1-2: input splits
    split4_kernel<<<dim3(NW / 1024, 4), 256>>>(q_w, k_w, v_w, out_w,
                                               wqh, wkh, wvh, woh,
                                               wql, wkl, wvl, wol, NW);
    split_kernel<<<NQ / 1024, 256>>>(query, qh, ql, NQ);
    split_kernel<<<NK / 1024, 256>>>(kv, kvh, kvl, NK);

    // launches 3-5: projections (launch 5 = V-proj -> captured by ncu -s 5 -c 1)
    cudaFuncSetAttribute(mma_gemm<0>, cudaFuncAttributeMaxDynamicSharedMemorySize, GEMM_SMEM);
    cudaFuncSetAttribute(mma_gemm<1>, cudaFuncAttributeMaxDynamicSharedMemorySize, GEMM_SMEM);
    cudaFuncSetAttribute(mma_gemm<2>, cudaFuncAttributeMaxDynamicSharedMemorySize, GEMM_SMEM);
    mma_gemm<2><<<dim3(8, 32), 256, GEMM_SMEM>>>(qh, ql, wqh, wql, q_b, nullptr,
                                                 aqh, aql, SQ, 2, 0.125f);
    mma_gemm<2><<<dim3(8, 64), 256, GEMM_SMEM>>>(kvh, kvl, wkh, wkl, k_b, nullptr,
                                                 akh, akl, SK, 1, 1.0f);
    mma_gemm<1><<<dim3(8, 64), 256, GEMM_SMEM>>>(kvh, kvl, wvh, wvl, v_b, nullptr,
                                                 avh, avl, 0, 0, 0.f);

    // tensor-core flash attention, bf16-split output
    cudaFuncSetAttribute(attn_mma, cudaFuncAttributeMaxDynamicSharedMemorySize, ATTN_SMEM);
    attn_mma<<<dim3(SQ / 128, NHEAD, NB), 256, ATTN_SMEM>>>(aqh, aql, akh, akl, avh, avl, oh, ol);

    // output projection (fp32 out)
    mma_gemm<0><<<dim3(8, 32), 256, GEMM_SMEM>>>(oh, ol, woh, wol, out_b, out,
                                                 nullptr, nullptr, 0, 0, 0.f);
}